// round 12
// baseline (speedup 1.0000x reference)
#include <cuda_runtime.h>
#include <cuda_bf16.h>
#include <stdint.h>
#include <math.h>

// Generator_causal via bf16 mma.sync, sync-free mainloop.
// R12: 1 m16-tile (16 rows) per warp, regs<=128 via __launch_bounds__(128,4)
// -> 16 warps/SM (4/SMSP) to feed the tensor unit past the 2-warp/SMSP wall.
// CTA = 64 rows / 4 warps; gmem fragment streams; z folded into fc epilogue.

#define XD 32
#define HD 128
#define TPB 128
#define ROWS 64

// smem: ZT [64][66B] z bf16 rows; OX [64][80B] o-state bf16 rows; MB [32][64B]
#define OFF_ZT 0
#define OFF_OX 4224
#define OFF_MB 9344
#define SMEM_BYTES 11392

// fragment images in global scratch (built by prep kernel)
__device__ uint2 g_WiF[32*16*2*32];   // [i][j][kk][lane] 256KB
__device__ uint4 g_W1F[16*4*32];      // [j][kkp][lane]   32KB
__device__ uint4 g_W2F[16*4*32];      // 32KB
__device__ float g_w32[32*128];       // Wi[:,32] per step 16KB

static __device__ __forceinline__ uint32_t pack_bf2(float lo, float hi){
    __nv_bfloat162 p = __floats2bfloat162_rn(lo, hi);
    return *(uint32_t*)&p;
}
static __device__ __forceinline__ uint32_t hmul2u(uint32_t a, uint32_t b){
    __nv_bfloat162 r = __hmul2(*(__nv_bfloat162*)&a, *(__nv_bfloat162*)&b);
    return *(uint32_t*)&r;
}
static __device__ __forceinline__ void mma_bf16(float* c, const uint32_t* a,
                                                uint32_t b0, uint32_t b1){
    asm volatile("mma.sync.aligned.m16n8k16.row.col.f32.bf16.bf16.f32 "
        "{%0,%1,%2,%3}, {%4,%5,%6,%7}, {%8,%9}, {%0,%1,%2,%3};"
        : "+f"(c[0]), "+f"(c[1]), "+f"(c[2]), "+f"(c[3])
        : "r"(a[0]), "r"(a[1]), "r"(a[2]), "r"(a[3]), "r"(b0), "r"(b1));
}
// zero-accumulator variant: writes C without reading it
static __device__ __forceinline__ void mma_bf16_z(float* c, const uint32_t* a,
                                                  uint32_t b0, uint32_t b1){
    float zz = 0.f;
    asm volatile("mma.sync.aligned.m16n8k16.row.col.f32.bf16.bf16.f32 "
        "{%0,%1,%2,%3}, {%4,%5,%6,%7}, {%8,%9}, {%10,%10,%10,%10};"
        : "=f"(c[0]), "=f"(c[1]), "=f"(c[2]), "=f"(c[3])
        : "r"(a[0]), "r"(a[1]), "r"(a[2]), "r"(a[3]), "r"(b0), "r"(b1), "f"(zz));
}

// ---------------- prep: bake fragment images ----------------
__global__ void prep_frag(const float* __restrict__ Wi,
                          const float* __restrict__ W1,
                          const float* __restrict__ W2){
    int idx = blockIdx.x * 256 + threadIdx.x;      // 32768 threads
    if (idx < 32*16*2*32){
        int lane = idx & 31, kk = (idx>>5)&1, j = (idx>>6)&15, i = idx>>10;
        int n = 8*j + (lane>>2), k0 = 16*kk + 2*(lane&3);
        const float* s = Wi + ((size_t)i*HD + n)*(XD+1);
        uint2 v;
        v.x = pack_bf2(s[k0],   s[k0+1]);
        v.y = pack_bf2(s[k0+8], s[k0+9]);
        g_WiF[idx] = v;
    }
    if (idx < 16*4*32){
        int lane = idx & 31, kkp = (idx>>5)&3, j = idx>>7;
        int n = 8*j + (lane>>2), kb = 32*kkp + 2*(lane&3);
        const float* s1 = W1 + n*HD;
        const float* s2 = W2 + n*HD;
        uint4 v1, v2;
        v1.x = pack_bf2(s1[kb],    s1[kb+1]);  v1.y = pack_bf2(s1[kb+8],  s1[kb+9]);
        v1.z = pack_bf2(s1[kb+16], s1[kb+17]); v1.w = pack_bf2(s1[kb+24], s1[kb+25]);
        v2.x = pack_bf2(s2[kb],    s2[kb+1]);  v2.y = pack_bf2(s2[kb+8],  s2[kb+9]);
        v2.z = pack_bf2(s2[kb+16], s2[kb+17]); v2.w = pack_bf2(s2[kb+24], s2[kb+25]);
        g_W1F[idx] = v1;
        g_W2F[idx] = v2;
    }
    if (idx < 32*128){
        int i = idx >> 7, n = idx & 127;
        g_w32[idx] = Wi[((size_t)i*HD + n)*(XD+1) + XD];
    }
}

// ---------------- main ----------------
__global__ void __launch_bounds__(TPB, 4) gen_causal_nf(
    const float* __restrict__ x,  const float* __restrict__ z,
    const float* __restrict__ M,
    const float* __restrict__ bi, const float* __restrict__ wf,
    const float* __restrict__ bf,
    const float* __restrict__ b1, const float* __restrict__ b2,
    float* __restrict__ out, int B)
{
    extern __shared__ char base[];
    char* ZTp = base + OFF_ZT;
    char* OXp = base + OFF_OX;
    char* MBp = base + OFF_MB;

    const int t    = threadIdx.x;
    const int lane = t & 31;
    const int warp = t >> 5;
    const int tq = lane & 3;
    const int g  = lane >> 2;
    const int ctaRow = blockIdx.x * ROWS;

    // ---- one-time init ----
    #pragma unroll 4
    for (int it = 0; it < 16; it++){
        int idx = it * TPB + t;                   // 2048 = 64x32
        int r = idx >> 5, c = idx & 31;
        float v = (ctaRow + r < B) ? z[(size_t)(ctaRow + r)*XD + c] : 0.f;
        __nv_bfloat16 h = __float2bfloat16(v);
        *(uint16_t*)(ZTp + r*66 + c*2) = *(uint16_t*)&h;
    }
    for (int idx = t; idx < 512; idx += TPB){
        int col = idx >> 4, p = idx & 15;
        *(uint32_t*)(MBp + col*64 + p*4) =
            pack_bf2(M[(2*p)*XD + col], M[(2*p+1)*XD + col]);
    }
    if (t < ROWS){   // o-state row t = x row (bf16)
        uint32_t* oxr = (uint32_t*)(OXp + t*80);
        int row = ctaRow + t;
        if (row < B){
            #pragma unroll
            for (int q = 0; q < 4; q++){
                float4 v = *(const float4*)(x + (size_t)row*XD + 4*q);
                oxr[2*q]   = pack_bf2(v.x, v.y);
                oxr[2*q+1] = pack_bf2(v.z, v.w);
            }
        } else {
            #pragma unroll
            for (int q = 0; q < 8; q++) oxr[q] = 0u;
        }
    }
    __syncthreads();   // the ONLY cta-wide sync

    const int rg0 = warp*16 + g;      // rows rg0, rg0+8 for this lane

    uint32_t A [8][4];   // fc output  (mlp1 input)
    uint32_t A2[8][4];   // mlp1 output (mlp2 input)

    for (int i = 0; i < XD; i++){
        // ---- fc A-frags directly from OX ⊙ M (warp-local rows) ----
        uint32_t afc[2][4];
        {
            #pragma unroll
            for (int kk = 0; kk < 2; kk++){
                uint32_t mlo = *(const uint32_t*)(MBp + i*64 + (8*kk+tq)*4);
                uint32_t mhi = *(const uint32_t*)(MBp + i*64 + (8*kk+4+tq)*4);
                afc[kk][0] = hmul2u(*(const uint32_t*)(OXp + rg0*80 + kk*32 + tq*4),          mlo);
                afc[kk][1] = hmul2u(*(const uint32_t*)(OXp + (rg0+8)*80 + kk*32 + tq*4),      mlo);
                afc[kk][2] = hmul2u(*(const uint32_t*)(OXp + rg0*80 + kk*32 + 16 + tq*4),     mhi);
                afc[kk][3] = hmul2u(*(const uint32_t*)(OXp + (rg0+8)*80 + kk*32 + 16 + tq*4), mhi);
            }
        }
        float zf0 = __bfloat162float(*(const __nv_bfloat16*)(ZTp + rg0*66 + 2*i));
        float zf1 = __bfloat162float(*(const __nv_bfloat16*)(ZTp + (rg0+8)*66 + 2*i));

        // ================= fc (K=32), two j-halves =================
        #pragma unroll
        for (int h = 0; h < 2; h++){
            float C8[8][4];
            const uint2* wif = g_WiF + (size_t)i*16*2*32;
            #pragma unroll
            for (int jj = 0; jj < 8; jj++){
                uint2 w0 = __ldg(&wif[((8*h+jj)*2 + 0)*32 + lane]);
                uint2 w1 = __ldg(&wif[((8*h+jj)*2 + 1)*32 + lane]);
                mma_bf16_z(C8[jj], afc[0], w0.x, w0.y);
                mma_bf16 (C8[jj], afc[1], w1.x, w1.y);
            }
            // fc epilogue for jp = 4h..4h+3
            #pragma unroll
            for (int q = 0; q < 4; q++){
                int jp = 4*h + q;
                float2 blo = __ldg((const float2*)(bi + i*HD + 16*jp + 2*tq));
                float2 bhi = __ldg((const float2*)(bi + i*HD + 16*jp + 8 + 2*tq));
                float2 wlo = __ldg((const float2*)(g_w32 + i*HD + 16*jp + 2*tq));
                float2 whi = __ldg((const float2*)(g_w32 + i*HD + 16*jp + 8 + 2*tq));
                float t00 = fmaf(zf0, wlo.x, blo.x);
                float t01 = fmaf(zf0, wlo.y, blo.y);
                float t10 = fmaf(zf1, wlo.x, blo.x);
                float t11 = fmaf(zf1, wlo.y, blo.y);
                float u00 = fmaf(zf0, whi.x, bhi.x);
                float u01 = fmaf(zf0, whi.y, bhi.y);
                float u10 = fmaf(zf1, whi.x, bhi.x);
                float u11 = fmaf(zf1, whi.y, bhi.y);
                const float* c0 = C8[2*q];
                const float* c1 = C8[2*q+1];
                A[jp][0] = pack_bf2(fmaxf(c0[0]+t00,0.f), fmaxf(c0[1]+t01,0.f));
                A[jp][1] = pack_bf2(fmaxf(c0[2]+t10,0.f), fmaxf(c0[3]+t11,0.f));
                A[jp][2] = pack_bf2(fmaxf(c1[0]+u00,0.f), fmaxf(c1[1]+u01,0.f));
                A[jp][3] = pack_bf2(fmaxf(c1[2]+u10,0.f), fmaxf(c1[3]+u11,0.f));
            }
        }

        // ================= MLP1 (W1, K=128), two j-halves =================
        #pragma unroll
        for (int h = 0; h < 2; h++){
            float C8[8][4];
            #pragma unroll
            for (int kkp = 0; kkp < 4; kkp++){
                #pragma unroll
                for (int jj = 0; jj < 8; jj++){
                    uint4 bv = __ldg(&g_W1F[((8*h+jj)*4 + kkp)*32 + lane]);
                    if (kkp == 0) mma_bf16_z(C8[jj], A[0], bv.x, bv.y);
                    else          mma_bf16 (C8[jj], A[2*kkp], bv.x, bv.y);
                    mma_bf16(C8[jj], A[2*kkp+1], bv.z, bv.w);
                }
            }
            // epilogue with b1 -> A2
            #pragma unroll
            for (int q = 0; q < 4; q++){
                int jp = 4*h + q;
                float2 blo = __ldg((const float2*)(b1 + 16*jp + 2*tq));
                float2 bhi = __ldg((const float2*)(b1 + 16*jp + 8 + 2*tq));
                const float* c0 = C8[2*q];
                const float* c1 = C8[2*q+1];
                A2[jp][0] = pack_bf2(fmaxf(c0[0]+blo.x,0.f), fmaxf(c0[1]+blo.y,0.f));
                A2[jp][1] = pack_bf2(fmaxf(c0[2]+blo.x,0.f), fmaxf(c0[3]+blo.y,0.f));
                A2[jp][2] = pack_bf2(fmaxf(c1[0]+bhi.x,0.f), fmaxf(c1[1]+bhi.y,0.f));
                A2[jp][3] = pack_bf2(fmaxf(c1[2]+bhi.x,0.f), fmaxf(c1[3]+bhi.y,0.f));
            }
        }

        // ================= MLP2 (W2, K=128) + final dot, two j-halves ========
        float p0 = 0.f, p1 = 0.f;
        #pragma unroll
        for (int h = 0; h < 2; h++){
            float C8[8][4];
            #pragma unroll
            for (int kkp = 0; kkp < 4; kkp++){
                #pragma unroll
                for (int jj = 0; jj < 8; jj++){
                    uint4 bv = __ldg(&g_W2F[((8*h+jj)*4 + kkp)*32 + lane]);
                    if (kkp == 0) mma_bf16_z(C8[jj], A2[0], bv.x, bv.y);
                    else          mma_bf16 (C8[jj], A2[2*kkp], bv.x, bv.y);
                    mma_bf16(C8[jj], A2[2*kkp+1], bv.z, bv.w);
                }
            }
            // final-dot partial for this half
            #pragma unroll
            for (int jj = 0; jj < 8; jj++){
                int j = 8*h + jj;
                float2 b2v = __ldg((const float2*)(b2 + 8*j + 2*tq));
                float2 wfv = __ldg((const float2*)(wf + i*HD + 8*j + 2*tq));
                p0 += fmaxf(C8[jj][0]+b2v.x, 0.f)*wfv.x
                    + fmaxf(C8[jj][1]+b2v.y, 0.f)*wfv.y;
                p1 += fmaxf(C8[jj][2]+b2v.x, 0.f)*wfv.x
                    + fmaxf(C8[jj][3]+b2v.y, 0.f)*wfv.y;
            }
        }

        // ---- sigmoid, state + out update ----
        {
            float bfv = __ldg(bf + i);
            p0 += __shfl_xor_sync(0xFFFFFFFFu, p0, 1);
            p0 += __shfl_xor_sync(0xFFFFFFFFu, p0, 2);
            p1 += __shfl_xor_sync(0xFFFFFFFFu, p1, 1);
            p1 += __shfl_xor_sync(0xFFFFFFFFu, p1, 2);
            if (tq == 0){
                int lr0 = rg0, lr1 = rg0 + 8;
                float v0 = 1.f/(1.f + __expf(-(p0 + bfv)));
                float v1 = 1.f/(1.f + __expf(-(p1 + bfv)));
                __nv_bfloat16 h0 = __float2bfloat16(v0);
                __nv_bfloat16 h1 = __float2bfloat16(v1);
                *(uint16_t*)(OXp + lr0*80 + 2*i) = *(uint16_t*)&h0;
                *(uint16_t*)(OXp + lr1*80 + 2*i) = *(uint16_t*)&h1;
                int gr0 = ctaRow + lr0, gr1 = ctaRow + lr1;
                if (gr0 < B) out[(size_t)gr0*XD + i] = v0;
                if (gr1 < B) out[(size_t)gr1*XD + i] = v1;
            }
        }
        __syncwarp();   // OX writes visible to this warp's next-step A-frag loads
    }
}

extern "C" void kernel_launch(void* const* d_in, const int* in_sizes, int n_in,
                              void* d_out, int out_size) {
    const float* x  = (const float*)d_in[0];
    const float* z  = (const float*)d_in[1];
    const float* M  = (const float*)d_in[2];
    const float* Wi = (const float*)d_in[3];
    const float* bi = (const float*)d_in[4];
    const float* wf = (const float*)d_in[5];
    const float* bf = (const float*)d_in[6];
    const float* W1 = (const float*)d_in[7];
    const float* b1 = (const float*)d_in[8];
    const float* W2 = (const float*)d_in[9];
    const float* b2 = (const float*)d_in[10];
    float* out = (float*)d_out;

    const int B = in_sizes[0] / XD;

    prep_frag<<<128, 256>>>(Wi, W1, W2);

    cudaFuncSetAttribute(gen_causal_nf,
                         cudaFuncAttributeMaxDynamicSharedMemorySize, SMEM_BYTES);
    const int grid = (B + ROWS - 1) / ROWS;
    gen_causal_nf<<<grid, TPB, SMEM_BYTES>>>(x, z, M, bi, wf, bf,
                                             b1, b2, out, B);
}

// round 13
// speedup vs baseline: 1.0207x; 1.0207x over previous
#include <cuda_runtime.h>
#include <cuda_bf16.h>
#include <stdint.h>
#include <math.h>

// Generator_causal via bf16 mma.sync, sync-free mainloop.
// R13: warp anti-phasing. Step = phase1 (fc+MLP1) + phase2 (MLP2+final).
// Odd warps run the loop offset by half a step, so the two warps sharing an
// SMSP sit at uncorrelated code positions: one issues MMAs while the other
// drains its epilogue. Config otherwise = R10 (2 m-tiles/warp, 128 rows/CTA).

#define XD 32
#define HD 128
#define TPB 128
#define ROWS 128

// smem: ZT [128][66B] z bf16 rows; OX [128][80B] o-state bf16 rows; MB [32][64B]
#define OFF_ZT 0
#define OFF_OX 8448
#define OFF_MB 18688
#define SMEM_BYTES 20736

__device__ uint2 g_WiF[32*16*2*32];   // [i][j][kk][lane] 256KB
__device__ uint4 g_W1F[16*4*32];      // [j][kkp][lane]   32KB
__device__ uint4 g_W2F[16*4*32];      // 32KB
__device__ float g_w32[32*128];       // Wi[:,32] per step 16KB

static __device__ __forceinline__ uint32_t pack_bf2(float lo, float hi){
    __nv_bfloat162 p = __floats2bfloat162_rn(lo, hi);
    return *(uint32_t*)&p;
}
static __device__ __forceinline__ uint32_t hmul2u(uint32_t a, uint32_t b){
    __nv_bfloat162 r = __hmul2(*(__nv_bfloat162*)&a, *(__nv_bfloat162*)&b);
    return *(uint32_t*)&r;
}
static __device__ __forceinline__ void mma_bf16(float* c, const uint32_t* a,
                                                uint32_t b0, uint32_t b1){
    asm volatile("mma.sync.aligned.m16n8k16.row.col.f32.bf16.bf16.f32 "
        "{%0,%1,%2,%3}, {%4,%5,%6,%7}, {%8,%9}, {%0,%1,%2,%3};"
        : "+f"(c[0]), "+f"(c[1]), "+f"(c[2]), "+f"(c[3])
        : "r"(a[0]), "r"(a[1]), "r"(a[2]), "r"(a[3]), "r"(b0), "r"(b1));
}
static __device__ __forceinline__ void mma_bf16_z(float* c, const uint32_t* a,
                                                  uint32_t b0, uint32_t b1){
    float zz = 0.f;
    asm volatile("mma.sync.aligned.m16n8k16.row.col.f32.bf16.bf16.f32 "
        "{%0,%1,%2,%3}, {%4,%5,%6,%7}, {%8,%9}, {%10,%10,%10,%10};"
        : "=f"(c[0]), "=f"(c[1]), "=f"(c[2]), "=f"(c[3])
        : "r"(a[0]), "r"(a[1]), "r"(a[2]), "r"(a[3]), "r"(b0), "r"(b1), "f"(zz));
}

// ---------------- prep: bake fragment images ----------------
__global__ void prep_frag(const float* __restrict__ Wi,
                          const float* __restrict__ W1,
                          const float* __restrict__ W2){
    int idx = blockIdx.x * 256 + threadIdx.x;      // 32768 threads
    if (idx < 32*16*2*32){
        int lane = idx & 31, kk = (idx>>5)&1, j = (idx>>6)&15, i = idx>>10;
        int n = 8*j + (lane>>2), k0 = 16*kk + 2*(lane&3);
        const float* s = Wi + ((size_t)i*HD + n)*(XD+1);
        uint2 v;
        v.x = pack_bf2(s[k0],   s[k0+1]);
        v.y = pack_bf2(s[k0+8], s[k0+9]);
        g_WiF[idx] = v;
    }
    if (idx < 16*4*32){
        int lane = idx & 31, kkp = (idx>>5)&3, j = idx>>7;
        int n = 8*j + (lane>>2), kb = 32*kkp + 2*(lane&3);
        const float* s1 = W1 + n*HD;
        const float* s2 = W2 + n*HD;
        uint4 v1, v2;
        v1.x = pack_bf2(s1[kb],    s1[kb+1]);  v1.y = pack_bf2(s1[kb+8],  s1[kb+9]);
        v1.z = pack_bf2(s1[kb+16], s1[kb+17]); v1.w = pack_bf2(s1[kb+24], s1[kb+25]);
        v2.x = pack_bf2(s2[kb],    s2[kb+1]);  v2.y = pack_bf2(s2[kb+8],  s2[kb+9]);
        v2.z = pack_bf2(s2[kb+16], s2[kb+17]); v2.w = pack_bf2(s2[kb+24], s2[kb+25]);
        g_W1F[idx] = v1;
        g_W2F[idx] = v2;
    }
    if (idx < 32*128){
        int i = idx >> 7, n = idx & 127;
        g_w32[idx] = Wi[((size_t)i*HD + n)*(XD+1) + XD];
    }
}

// ---------------- main ----------------
__global__ void __launch_bounds__(TPB, 2) gen_causal_nf(
    const float* __restrict__ x,  const float* __restrict__ z,
    const float* __restrict__ M,
    const float* __restrict__ bi, const float* __restrict__ wf,
    const float* __restrict__ bf,
    const float* __restrict__ b1, const float* __restrict__ b2,
    float* __restrict__ out, int B)
{
    extern __shared__ char base[];
    char* ZTp = base + OFF_ZT;
    char* OXp = base + OFF_OX;
    char* MBp = base + OFF_MB;

    const int t    = threadIdx.x;
    const int lane = t & 31;
    const int warp = t >> 5;
    const int wbase = warp * 32;
    const int tq = lane & 3;
    const int g  = lane >> 2;
    const int ctaRow = blockIdx.x * ROWS;
    const int row = ctaRow + t;
    const bool active = (row < B);

    // ---- one-time init ----
    #pragma unroll 4
    for (int it = 0; it < 32; it++){
        int idx = it * TPB + t;                   // 4096 = 128x32
        int r = idx >> 5, c = idx & 31;
        float v = (ctaRow + r < B) ? z[(size_t)(ctaRow + r)*XD + c] : 0.f;
        __nv_bfloat16 h = __float2bfloat16(v);
        *(uint16_t*)(ZTp + r*66 + c*2) = *(uint16_t*)&h;
    }
    for (int idx = t; idx < 512; idx += TPB){
        int col = idx >> 4, p = idx & 15;
        *(uint32_t*)(MBp + col*64 + p*4) =
            pack_bf2(M[(2*p)*XD + col], M[(2*p+1)*XD + col]);
    }
    {
        uint32_t* oxr = (uint32_t*)(OXp + t*80);
        if (active){
            #pragma unroll
            for (int q = 0; q < 4; q++){
                float4 v = *(const float4*)(x + (size_t)row*XD + 4*q);
                oxr[2*q]   = pack_bf2(v.x, v.y);
                oxr[2*q+1] = pack_bf2(v.z, v.w);
            }
        } else {
            #pragma unroll
            for (int q = 0; q < 8; q++) oxr[q] = 0u;
        }
    }
    __syncthreads();   // the ONLY cta-wide sync

    const int rg0 = wbase + g;        // m=0 rows: rg0, rg0+8
    const int rg1 = wbase + 16 + g;   // m=1 rows

    uint32_t A [2][8][4];   // fc output  (mlp1 input)
    uint32_t A2[2][8][4];   // mlp1 output (mlp2 input)

    // ---------- phase1: fc + MLP1 for step i -> A2 ----------
    auto phase1 = [&](int i){
        uint32_t afc[2][2][4];
        #pragma unroll
        for (int m = 0; m < 2; m++){
            int rg = m ? rg1 : rg0;
            #pragma unroll
            for (int kk = 0; kk < 2; kk++){
                uint32_t mlo = *(const uint32_t*)(MBp + i*64 + (8*kk+tq)*4);
                uint32_t mhi = *(const uint32_t*)(MBp + i*64 + (8*kk+4+tq)*4);
                afc[m][kk][0] = hmul2u(*(const uint32_t*)(OXp + rg*80 + kk*32 + tq*4),          mlo);
                afc[m][kk][1] = hmul2u(*(const uint32_t*)(OXp + (rg+8)*80 + kk*32 + tq*4),      mlo);
                afc[m][kk][2] = hmul2u(*(const uint32_t*)(OXp + rg*80 + kk*32 + 16 + tq*4),     mhi);
                afc[m][kk][3] = hmul2u(*(const uint32_t*)(OXp + (rg+8)*80 + kk*32 + 16 + tq*4), mhi);
            }
        }
        float zf[2][2];
        #pragma unroll
        for (int m = 0; m < 2; m++){
            int rg = m ? rg1 : rg0;
            zf[m][0] = __bfloat162float(*(const __nv_bfloat16*)(ZTp + rg*66 + 2*i));
            zf[m][1] = __bfloat162float(*(const __nv_bfloat16*)(ZTp + (rg+8)*66 + 2*i));
        }

        // fc (K=32), two j-halves
        #pragma unroll
        for (int h = 0; h < 2; h++){
            float C8[2][8][4];
            const uint2* wif = g_WiF + (size_t)i*16*2*32;
            #pragma unroll
            for (int jj = 0; jj < 8; jj++){
                uint2 w0 = __ldg(&wif[((8*h+jj)*2 + 0)*32 + lane]);
                uint2 w1 = __ldg(&wif[((8*h+jj)*2 + 1)*32 + lane]);
                mma_bf16_z(C8[0][jj], afc[0][0], w0.x, w0.y);
                mma_bf16 (C8[0][jj], afc[0][1], w1.x, w1.y);
                mma_bf16_z(C8[1][jj], afc[1][0], w0.x, w0.y);
                mma_bf16 (C8[1][jj], afc[1][1], w1.x, w1.y);
            }
            #pragma unroll
            for (int q = 0; q < 4; q++){
                int jp = 4*h + q;
                float2 blo = __ldg((const float2*)(bi + i*HD + 16*jp + 2*tq));
                float2 bhi = __ldg((const float2*)(bi + i*HD + 16*jp + 8 + 2*tq));
                float2 wlo = __ldg((const float2*)(g_w32 + i*HD + 16*jp + 2*tq));
                float2 whi = __ldg((const float2*)(g_w32 + i*HD + 16*jp + 8 + 2*tq));
                #pragma unroll
                for (int m = 0; m < 2; m++){
                    float t00 = fmaf(zf[m][0], wlo.x, blo.x);
                    float t01 = fmaf(zf[m][0], wlo.y, blo.y);
                    float t10 = fmaf(zf[m][1], wlo.x, blo.x);
                    float t11 = fmaf(zf[m][1], wlo.y, blo.y);
                    float u00 = fmaf(zf[m][0], whi.x, bhi.x);
                    float u01 = fmaf(zf[m][0], whi.y, bhi.y);
                    float u10 = fmaf(zf[m][1], whi.x, bhi.x);
                    float u11 = fmaf(zf[m][1], whi.y, bhi.y);
                    const float* c0 = C8[m][2*q];
                    const float* c1 = C8[m][2*q+1];
                    A[m][jp][0] = pack_bf2(fmaxf(c0[0]+t00,0.f), fmaxf(c0[1]+t01,0.f));
                    A[m][jp][1] = pack_bf2(fmaxf(c0[2]+t10,0.f), fmaxf(c0[3]+t11,0.f));
                    A[m][jp][2] = pack_bf2(fmaxf(c1[0]+u00,0.f), fmaxf(c1[1]+u01,0.f));
                    A[m][jp][3] = pack_bf2(fmaxf(c1[2]+u10,0.f), fmaxf(c1[3]+u11,0.f));
                }
            }
        }

        // MLP1 (W1, K=128), two j-halves
        #pragma unroll
        for (int h = 0; h < 2; h++){
            float C8[2][8][4];
            #pragma unroll
            for (int jj = 0; jj < 8; jj++){
                int j = 8*h + jj;
                #pragma unroll
                for (int kkp = 0; kkp < 4; kkp++){
                    uint4 bv = __ldg(&g_W1F[(j*4+kkp)*32 + lane]);
                    if (kkp == 0){
                        mma_bf16_z(C8[0][jj], A[0][0], bv.x, bv.y);
                        mma_bf16_z(C8[1][jj], A[1][0], bv.x, bv.y);
                    } else {
                        mma_bf16(C8[0][jj], A[0][2*kkp], bv.x, bv.y);
                        mma_bf16(C8[1][jj], A[1][2*kkp], bv.x, bv.y);
                    }
                    mma_bf16(C8[0][jj], A[0][2*kkp+1], bv.z, bv.w);
                    mma_bf16(C8[1][jj], A[1][2*kkp+1], bv.z, bv.w);
                }
            }
            #pragma unroll
            for (int q = 0; q < 4; q++){
                int jp = 4*h + q;
                float2 blo = __ldg((const float2*)(b1 + 16*jp + 2*tq));
                float2 bhi = __ldg((const float2*)(b1 + 16*jp + 8 + 2*tq));
                #pragma unroll
                for (int m = 0; m < 2; m++){
                    const float* c0 = C8[m][2*q];
                    const float* c1 = C8[m][2*q+1];
                    A2[m][jp][0] = pack_bf2(fmaxf(c0[0]+blo.x,0.f), fmaxf(c0[1]+blo.y,0.f));
                    A2[m][jp][1] = pack_bf2(fmaxf(c0[2]+blo.x,0.f), fmaxf(c0[3]+blo.y,0.f));
                    A2[m][jp][2] = pack_bf2(fmaxf(c1[0]+bhi.x,0.f), fmaxf(c1[1]+bhi.y,0.f));
                    A2[m][jp][3] = pack_bf2(fmaxf(c1[2]+bhi.x,0.f), fmaxf(c1[3]+bhi.y,0.f));
                }
            }
        }
    };

    // ---------- phase2: MLP2 + final dot + state update for step i ----------
    auto phase2 = [&](int i){
        float p0[2] = {0.f, 0.f}, p1[2] = {0.f, 0.f};
        #pragma unroll
        for (int h = 0; h < 2; h++){
            float C8[2][8][4];
            #pragma unroll
            for (int jj = 0; jj < 8; jj++){
                int j = 8*h + jj;
                #pragma unroll
                for (int kkp = 0; kkp < 4; kkp++){
                    uint4 bv = __ldg(&g_W2F[(j*4+kkp)*32 + lane]);
                    if (kkp == 0){
                        mma_bf16_z(C8[0][jj], A2[0][0], bv.x, bv.y);
                        mma_bf16_z(C8[1][jj], A2[1][0], bv.x, bv.y);
                    } else {
                        mma_bf16(C8[0][jj], A2[0][2*kkp], bv.x, bv.y);
                        mma_bf16(C8[1][jj], A2[1][2*kkp], bv.x, bv.y);
                    }
                    mma_bf16(C8[0][jj], A2[0][2*kkp+1], bv.z, bv.w);
                    mma_bf16(C8[1][jj], A2[1][2*kkp+1], bv.z, bv.w);
                }
            }
            #pragma unroll
            for (int jj = 0; jj < 8; jj++){
                int j = 8*h + jj;
                float2 b2v = __ldg((const float2*)(b2 + 8*j + 2*tq));
                float2 wfv = __ldg((const float2*)(wf + i*HD + 8*j + 2*tq));
                #pragma unroll
                for (int m = 0; m < 2; m++){
                    p0[m] += fmaxf(C8[m][jj][0]+b2v.x, 0.f)*wfv.x
                           + fmaxf(C8[m][jj][1]+b2v.y, 0.f)*wfv.y;
                    p1[m] += fmaxf(C8[m][jj][2]+b2v.x, 0.f)*wfv.x
                           + fmaxf(C8[m][jj][3]+b2v.y, 0.f)*wfv.y;
                }
            }
        }
        float bfv = __ldg(bf + i);
        #pragma unroll
        for (int m = 0; m < 2; m++){
            float q0 = p0[m], q1 = p1[m];
            q0 += __shfl_xor_sync(0xFFFFFFFFu, q0, 1);
            q0 += __shfl_xor_sync(0xFFFFFFFFu, q0, 2);
            q1 += __shfl_xor_sync(0xFFFFFFFFu, q1, 1);
            q1 += __shfl_xor_sync(0xFFFFFFFFu, q1, 2);
            if (tq == 0){
                int lr0 = (m ? rg1 : rg0);
                int lr1 = lr0 + 8;
                float v0 = 1.f/(1.f + __expf(-(q0 + bfv)));
                float v1 = 1.f/(1.f + __expf(-(q1 + bfv)));
                __nv_bfloat16 h0 = __float2bfloat16(v0);
                __nv_bfloat16 h1 = __float2bfloat16(v1);
                *(uint16_t*)(OXp + lr0*80 + 2*i) = *(uint16_t*)&h0;
                *(uint16_t*)(OXp + lr1*80 + 2*i) = *(uint16_t*)&h1;
                int gr0 = ctaRow + lr0, gr1 = ctaRow + lr1;
                if (gr0 < B) out[(size_t)gr0*XD + i] = v0;
                if (gr1 < B) out[(size_t)gr1*XD + i] = v1;
            }
        }
        __syncwarp();   // OX writes visible before next phase1 reads
    };

    // ---------- anti-phased loops ----------
    if (warp & 1){
        phase1(0);
        for (int i = 0; i < XD-1; i++){
            phase2(i);
            phase1(i+1);
        }
        phase2(XD-1);
    } else {
        for (int i = 0; i < XD; i++){
            phase1(i);
            phase2(i);
        }
    }
}

extern "C" void kernel_launch(void* const* d_in, const int* in_sizes, int n_in,
                              void* d_out, int out_size) {
    const float* x  = (const float*)d_in[0];
    const float* z  = (const float*)d_in[1];
    const float* M  = (const float*)d_in[2];
    const float* Wi = (const float*)d_in[3];
    const float* bi = (const float*)d_in[4];
    const float* wf = (const float*)d_in[5];
    const float* bf = (const float*)d_in[6];
    const float* W1 = (const float*)d_in[7];
    const float* b1 = (const float*)d_in[8];
    const float* W2 = (const float*)d_in[9];
    const float* b2 = (const float*)d_in[10];
    float* out = (float*)d_out;

    const int B = in_sizes[0] / XD;

    prep_frag<<<128, 256>>>(Wi, W1, W2);

    cudaFuncSetAttribute(gen_causal_nf,
                         cudaFuncAttributeMaxDynamicSharedMemorySize, SMEM_BYTES);
    const int grid = (B + ROWS - 1) / ROWS;
    gen_causal_nf<<<grid, TPB, SMEM_BYTES>>>(x, z, M, bi, wf, bf,
                                             b1, b2, out, B);
}

// round 14
// speedup vs baseline: 1.1683x; 1.1446x over previous
#include <cuda_runtime.h>
#include <cuda_bf16.h>
#include <stdint.h>
#include <math.h>

// Generator_causal via bf16 mma.sync, sync-free mainloop (R10 body).
// R14: CTA time-skew. Co-resident CTAs on an SM take opposite-parity tickets
// (per-SM atomic counter); odd-slot CTAs burn ~half a step period before the
// loop. The two warps sharing each SMSP then run identical code half a step
// out of phase: one issues MMAs while the other drains its epilogue.

#define XD 32
#define HD 128
#define TPB 128
#define ROWS 128

// smem: ZT [128][66B]; OX [128][80B]; MB [32][64B]; TK (4B)
#define OFF_ZT 0
#define OFF_OX 8448
#define OFF_MB 18688
#define OFF_TK 20736
#define SMEM_BYTES 20864

__device__ uint2 g_WiF[32*16*2*32];   // [i][j][kk][lane] 256KB
__device__ uint4 g_W1F[16*4*32];      // [j][kkp][lane]   32KB
__device__ uint4 g_W2F[16*4*32];      // 32KB
__device__ float g_w32[32*128];       // Wi[:,32] per step 16KB
__device__ unsigned g_ticket[1024];   // per-SM arrival counter

static __device__ __forceinline__ uint32_t pack_bf2(float lo, float hi){
    __nv_bfloat162 p = __floats2bfloat162_rn(lo, hi);
    return *(uint32_t*)&p;
}
static __device__ __forceinline__ uint32_t hmul2u(uint32_t a, uint32_t b){
    __nv_bfloat162 r = __hmul2(*(__nv_bfloat162*)&a, *(__nv_bfloat162*)&b);
    return *(uint32_t*)&r;
}
static __device__ __forceinline__ void mma_bf16(float* c, const uint32_t* a,
                                                uint32_t b0, uint32_t b1){
    asm volatile("mma.sync.aligned.m16n8k16.row.col.f32.bf16.bf16.f32 "
        "{%0,%1,%2,%3}, {%4,%5,%6,%7}, {%8,%9}, {%0,%1,%2,%3};"
        : "+f"(c[0]), "+f"(c[1]), "+f"(c[2]), "+f"(c[3])
        : "r"(a[0]), "r"(a[1]), "r"(a[2]), "r"(a[3]), "r"(b0), "r"(b1));
}
static __device__ __forceinline__ void mma_bf16_z(float* c, const uint32_t* a,
                                                  uint32_t b0, uint32_t b1){
    float zz = 0.f;
    asm volatile("mma.sync.aligned.m16n8k16.row.col.f32.bf16.bf16.f32 "
        "{%0,%1,%2,%3}, {%4,%5,%6,%7}, {%8,%9}, {%10,%10,%10,%10};"
        : "=f"(c[0]), "=f"(c[1]), "=f"(c[2]), "=f"(c[3])
        : "r"(a[0]), "r"(a[1]), "r"(a[2]), "r"(a[3]), "r"(b0), "r"(b1), "f"(zz));
}

// ---------------- prep: bake fragment images ----------------
__global__ void prep_frag(const float* __restrict__ Wi,
                          const float* __restrict__ W1,
                          const float* __restrict__ W2){
    int idx = blockIdx.x * 256 + threadIdx.x;      // 32768 threads
    if (idx < 32*16*2*32){
        int lane = idx & 31, kk = (idx>>5)&1, j = (idx>>6)&15, i = idx>>10;
        int n = 8*j + (lane>>2), k0 = 16*kk + 2*(lane&3);
        const float* s = Wi + ((size_t)i*HD + n)*(XD+1);
        uint2 v;
        v.x = pack_bf2(s[k0],   s[k0+1]);
        v.y = pack_bf2(s[k0+8], s[k0+9]);
        g_WiF[idx] = v;
    }
    if (idx < 16*4*32){
        int lane = idx & 31, kkp = (idx>>5)&3, j = idx>>7;
        int n = 8*j + (lane>>2), kb = 32*kkp + 2*(lane&3);
        const float* s1 = W1 + n*HD;
        const float* s2 = W2 + n*HD;
        uint4 v1, v2;
        v1.x = pack_bf2(s1[kb],    s1[kb+1]);  v1.y = pack_bf2(s1[kb+8],  s1[kb+9]);
        v1.z = pack_bf2(s1[kb+16], s1[kb+17]); v1.w = pack_bf2(s1[kb+24], s1[kb+25]);
        v2.x = pack_bf2(s2[kb],    s2[kb+1]);  v2.y = pack_bf2(s2[kb+8],  s2[kb+9]);
        v2.z = pack_bf2(s2[kb+16], s2[kb+17]); v2.w = pack_bf2(s2[kb+24], s2[kb+25]);
        g_W1F[idx] = v1;
        g_W2F[idx] = v2;
    }
    if (idx < 32*128){
        int i = idx >> 7, n = idx & 127;
        g_w32[idx] = Wi[((size_t)i*HD + n)*(XD+1) + XD];
    }
}

// ---------------- main ----------------
__global__ void __launch_bounds__(TPB, 2) gen_causal_nf(
    const float* __restrict__ x,  const float* __restrict__ z,
    const float* __restrict__ M,
    const float* __restrict__ bi, const float* __restrict__ wf,
    const float* __restrict__ bf,
    const float* __restrict__ b1, const float* __restrict__ b2,
    float* __restrict__ out, int B)
{
    extern __shared__ char base[];
    char* ZTp = base + OFF_ZT;
    char* OXp = base + OFF_OX;
    char* MBp = base + OFF_MB;

    const int t    = threadIdx.x;
    const int lane = t & 31;
    const int warp = t >> 5;
    const int wbase = warp * 32;
    const int tq = lane & 3;
    const int g  = lane >> 2;
    const int ctaRow = blockIdx.x * ROWS;
    const int row = ctaRow + t;
    const bool active = (row < B);

    // ---- per-SM co-residency ticket ----
    if (t == 0){
        uint32_t smid;
        asm volatile("mov.u32 %0, %%smid;" : "=r"(smid));
        unsigned tk = atomicAdd(&g_ticket[smid & 1023], 1u);
        *(unsigned*)(base + OFF_TK) = tk;
    }

    // ---- one-time init ----
    #pragma unroll 4
    for (int it = 0; it < 32; it++){
        int idx = it * TPB + t;                   // 4096 = 128x32
        int r = idx >> 5, c = idx & 31;
        float v = (ctaRow + r < B) ? z[(size_t)(ctaRow + r)*XD + c] : 0.f;
        __nv_bfloat16 h = __float2bfloat16(v);
        *(uint16_t*)(ZTp + r*66 + c*2) = *(uint16_t*)&h;
    }
    for (int idx = t; idx < 512; idx += TPB){
        int col = idx >> 4, p = idx & 15;
        *(uint32_t*)(MBp + col*64 + p*4) =
            pack_bf2(M[(2*p)*XD + col], M[(2*p+1)*XD + col]);
    }
    {
        uint32_t* oxr = (uint32_t*)(OXp + t*80);
        if (active){
            #pragma unroll
            for (int q = 0; q < 4; q++){
                float4 v = *(const float4*)(x + (size_t)row*XD + 4*q);
                oxr[2*q]   = pack_bf2(v.x, v.y);
                oxr[2*q+1] = pack_bf2(v.z, v.w);
            }
        } else {
            #pragma unroll
            for (int q = 0; q < 8; q++) oxr[q] = 0u;
        }
    }
    __syncthreads();   // the ONLY cta-wide sync

    // ---- anti-phase burn: odd-slot CTAs start ~half a step late ----
    if ((*(volatile unsigned*)(base + OFF_TK)) & 1u){
        float acc = (float)t * 1e-20f;
        for (int k = 0; k < 2400; k++)
            asm volatile("fma.rn.f32 %0, %0, %1, %2;"
                         : "+f"(acc) : "f"(1.0000001f), "f"(1e-30f));
        if (acc > 1e10f) ((volatile float*)base)[0] = acc;  // never true
    }

    const int rg0 = wbase + g;        // m=0 rows: rg0, rg0+8
    const int rg1 = wbase + 16 + g;   // m=1 rows

    uint32_t A [2][8][4];   // fc output  (mlp1 input)
    uint32_t A2[2][8][4];   // mlp1 output (mlp2 input)

    for (int i = 0; i < XD; i++){
        // ---- fc A-frags directly from OX ⊙ M (warp-local rows) ----
        uint32_t afc[2][2][4];
        #pragma unroll
        for (int m = 0; m < 2; m++){
            int rg = m ? rg1 : rg0;
            #pragma unroll
            for (int kk = 0; kk < 2; kk++){
                uint32_t mlo = *(const uint32_t*)(MBp + i*64 + (8*kk+tq)*4);
                uint32_t mhi = *(const uint32_t*)(MBp + i*64 + (8*kk+4+tq)*4);
                afc[m][kk][0] = hmul2u(*(const uint32_t*)(OXp + rg*80 + kk*32 + tq*4),          mlo);
                afc[m][kk][1] = hmul2u(*(const uint32_t*)(OXp + (rg+8)*80 + kk*32 + tq*4),      mlo);
                afc[m][kk][2] = hmul2u(*(const uint32_t*)(OXp + rg*80 + kk*32 + 16 + tq*4),     mhi);
                afc[m][kk][3] = hmul2u(*(const uint32_t*)(OXp + (rg+8)*80 + kk*32 + 16 + tq*4), mhi);
            }
        }

        float zf[2][2];
        #pragma unroll
        for (int m = 0; m < 2; m++){
            int rg = m ? rg1 : rg0;
            zf[m][0] = __bfloat162float(*(const __nv_bfloat16*)(ZTp + rg*66 + 2*i));
            zf[m][1] = __bfloat162float(*(const __nv_bfloat16*)(ZTp + (rg+8)*66 + 2*i));
        }

        // ================= fc (K=32), two j-halves =================
        #pragma unroll
        for (int h = 0; h < 2; h++){
            float C8[2][8][4];
            const uint2* wif = g_WiF + (size_t)i*16*2*32;
            #pragma unroll
            for (int jj = 0; jj < 8; jj++){
                uint2 w0 = __ldg(&wif[((8*h+jj)*2 + 0)*32 + lane]);
                uint2 w1 = __ldg(&wif[((8*h+jj)*2 + 1)*32 + lane]);
                mma_bf16_z(C8[0][jj], afc[0][0], w0.x, w0.y);
                mma_bf16 (C8[0][jj], afc[0][1], w1.x, w1.y);
                mma_bf16_z(C8[1][jj], afc[1][0], w0.x, w0.y);
                mma_bf16 (C8[1][jj], afc[1][1], w1.x, w1.y);
            }
            // fc epilogue for jp = 4h..4h+3
            #pragma unroll
            for (int q = 0; q < 4; q++){
                int jp = 4*h + q;
                float2 blo = __ldg((const float2*)(bi + i*HD + 16*jp + 2*tq));
                float2 bhi = __ldg((const float2*)(bi + i*HD + 16*jp + 8 + 2*tq));
                float2 wlo = __ldg((const float2*)(g_w32 + i*HD + 16*jp + 2*tq));
                float2 whi = __ldg((const float2*)(g_w32 + i*HD + 16*jp + 8 + 2*tq));
                #pragma unroll
                for (int m = 0; m < 2; m++){
                    float t00 = fmaf(zf[m][0], wlo.x, blo.x);
                    float t01 = fmaf(zf[m][0], wlo.y, blo.y);
                    float t10 = fmaf(zf[m][1], wlo.x, blo.x);
                    float t11 = fmaf(zf[m][1], wlo.y, blo.y);
                    float u00 = fmaf(zf[m][0], whi.x, bhi.x);
                    float u01 = fmaf(zf[m][0], whi.y, bhi.y);
                    float u10 = fmaf(zf[m][1], whi.x, bhi.x);
                    float u11 = fmaf(zf[m][1], whi.y, bhi.y);
                    const float* c0 = C8[m][2*q];
                    const float* c1 = C8[m][2*q+1];
                    A[m][jp][0] = pack_bf2(fmaxf(c0[0]+t00,0.f), fmaxf(c0[1]+t01,0.f));
                    A[m][jp][1] = pack_bf2(fmaxf(c0[2]+t10,0.f), fmaxf(c0[3]+t11,0.f));
                    A[m][jp][2] = pack_bf2(fmaxf(c1[0]+u00,0.f), fmaxf(c1[1]+u01,0.f));
                    A[m][jp][3] = pack_bf2(fmaxf(c1[2]+u10,0.f), fmaxf(c1[3]+u11,0.f));
                }
            }
        }

        // ================= MLP1 (W1, K=128), two j-halves =================
        #pragma unroll
        for (int h = 0; h < 2; h++){
            float C8[2][8][4];
            #pragma unroll
            for (int jj = 0; jj < 8; jj++){
                int j = 8*h + jj;
                #pragma unroll
                for (int kkp = 0; kkp < 4; kkp++){
                    uint4 bv = __ldg(&g_W1F[(j*4+kkp)*32 + lane]);
                    if (kkp == 0){
                        mma_bf16_z(C8[0][jj], A[0][0], bv.x, bv.y);
                        mma_bf16_z(C8[1][jj], A[1][0], bv.x, bv.y);
                    } else {
                        mma_bf16(C8[0][jj], A[0][2*kkp], bv.x, bv.y);
                        mma_bf16(C8[1][jj], A[1][2*kkp], bv.x, bv.y);
                    }
                    mma_bf16(C8[0][jj], A[0][2*kkp+1], bv.z, bv.w);
                    mma_bf16(C8[1][jj], A[1][2*kkp+1], bv.z, bv.w);
                }
            }
            // epilogue with b1 -> A2
            #pragma unroll
            for (int q = 0; q < 4; q++){
                int jp = 4*h + q;
                float2 blo = __ldg((const float2*)(b1 + 16*jp + 2*tq));
                float2 bhi = __ldg((const float2*)(b1 + 16*jp + 8 + 2*tq));
                #pragma unroll
                for (int m = 0; m < 2; m++){
                    const float* c0 = C8[m][2*q];
                    const float* c1 = C8[m][2*q+1];
                    A2[m][jp][0] = pack_bf2(fmaxf(c0[0]+blo.x,0.f), fmaxf(c0[1]+blo.y,0.f));
                    A2[m][jp][1] = pack_bf2(fmaxf(c0[2]+blo.x,0.f), fmaxf(c0[3]+blo.y,0.f));
                    A2[m][jp][2] = pack_bf2(fmaxf(c1[0]+bhi.x,0.f), fmaxf(c1[1]+bhi.y,0.f));
                    A2[m][jp][3] = pack_bf2(fmaxf(c1[2]+bhi.x,0.f), fmaxf(c1[3]+bhi.y,0.f));
                }
            }
        }

        // ================= MLP2 (W2, K=128) + final dot, two j-halves ========
        float p0[2] = {0.f, 0.f}, p1[2] = {0.f, 0.f};
        #pragma unroll
        for (int h = 0; h < 2; h++){
            float C8[2][8][4];
            #pragma unroll
            for (int jj = 0; jj < 8; jj++){
                int j = 8*h + jj;
                #pragma unroll
                for (int kkp = 0; kkp < 4; kkp++){
                    uint4 bv = __ldg(&g_W2F[(j*4+kkp)*32 + lane]);
                    if (kkp == 0){
                        mma_bf16_z(C8[0][jj], A2[0][0], bv.x, bv.y);
                        mma_bf16_z(C8[1][jj], A2[1][0], bv.x, bv.y);
                    } else {
                        mma_bf16(C8[0][jj], A2[0][2*kkp], bv.x, bv.y);
                        mma_bf16(C8[1][jj], A2[1][2*kkp], bv.x, bv.y);
                    }
                    mma_bf16(C8[0][jj], A2[0][2*kkp+1], bv.z, bv.w);
                    mma_bf16(C8[1][jj], A2[1][2*kkp+1], bv.z, bv.w);
                }
            }
            // final-dot partial for this half
            #pragma unroll
            for (int jj = 0; jj < 8; jj++){
                int j = 8*h + jj;
                float2 b2v = __ldg((const float2*)(b2 + 8*j + 2*tq));
                float2 wfv = __ldg((const float2*)(wf + i*HD + 8*j + 2*tq));
                #pragma unroll
                for (int m = 0; m < 2; m++){
                    p0[m] += fmaxf(C8[m][jj][0]+b2v.x, 0.f)*wfv.x
                           + fmaxf(C8[m][jj][1]+b2v.y, 0.f)*wfv.y;
                    p1[m] += fmaxf(C8[m][jj][2]+b2v.x, 0.f)*wfv.x
                           + fmaxf(C8[m][jj][3]+b2v.y, 0.f)*wfv.y;
                }
            }
        }

        // ---- sigmoid, state + out update ----
        {
            float bfv = __ldg(bf + i);
            #pragma unroll
            for (int m = 0; m < 2; m++){
                float q0 = p0[m], q1 = p1[m];
                q0 += __shfl_xor_sync(0xFFFFFFFFu, q0, 1);
                q0 += __shfl_xor_sync(0xFFFFFFFFu, q0, 2);
                q1 += __shfl_xor_sync(0xFFFFFFFFu, q1, 1);
                q1 += __shfl_xor_sync(0xFFFFFFFFu, q1, 2);
                if (tq == 0){
                    int lr0 = (m ? rg1 : rg0);
                    int lr1 = lr0 + 8;
                    float v0 = 1.f/(1.f + __expf(-(q0 + bfv)));
                    float v1 = 1.f/(1.f + __expf(-(q1 + bfv)));
                    __nv_bfloat16 h0 = __float2bfloat16(v0);
                    __nv_bfloat16 h1 = __float2bfloat16(v1);
                    *(uint16_t*)(OXp + lr0*80 + 2*i) = *(uint16_t*)&h0;
                    *(uint16_t*)(OXp + lr1*80 + 2*i) = *(uint16_t*)&h1;
                    int gr0 = ctaRow + lr0, gr1 = ctaRow + lr1;
                    if (gr0 < B) out[(size_t)gr0*XD + i] = v0;
                    if (gr1 < B) out[(size_t)gr1*XD + i] = v1;
                }
            }
        }
        __syncwarp();   // OX writes visible to this warp's next-step A-frag loads
    }
}

extern "C" void kernel_launch(void* const* d_in, const int* in_sizes, int n_in,
                              void* d_out, int out_size) {
    const float* x  = (const float*)d_in[0];
    const float* z  = (const float*)d_in[1];
    const float* M  = (const float*)d_in[2];
    const float* Wi = (const float*)d_in[3];
    const float* bi = (const float*)d_in[4];
    const float* wf = (const float*)d_in[5];
    const float* bf = (const float*)d_in[6];
    const float* W1 = (const float*)d_in[7];
    const float* b1 = (const float*)d_in[8];
    const float* W2 = (const float*)d_in[9];
    const float* b2 = (const float*)d_in[10];
    float* out = (float*)d_out;

    const int B = in_sizes[0] / XD;

    prep_frag<<<128, 256>>>(Wi, W1, W2);

    cudaFuncSetAttribute(gen_causal_nf,
                         cudaFuncAttributeMaxDynamicSharedMemorySize, SMEM_BYTES);
    const int grid = (B + ROWS - 1) / ROWS;
    gen_causal_nf<<<grid, TPB, SMEM_BYTES>>>(x, z, M, bi, wf, bf,
                                             b1, b2, out, B);
}

// round 15
// speedup vs baseline: 1.1985x; 1.0258x over previous
#include <cuda_runtime.h>
#include <cuda_bf16.h>
#include <stdint.h>
#include <math.h>

// Generator_causal via bf16 mma.sync, sync-free mainloop (R14 + packed epilogues).
// R15: epilogues use bf16x2 hadd2/hmax2 (3 ops per pair vs 5 fp32 ops);
// b1 pre-packed to bf16x2 fragments in prep. CTA time-skew kept from R14.

#define XD 32
#define HD 128
#define TPB 128
#define ROWS 128

// smem: ZT [128][66B]; OX [128][80B]; MB [32][64B]; TK (4B)
#define OFF_ZT 0
#define OFF_OX 8448
#define OFF_MB 18688
#define OFF_TK 20736
#define SMEM_BYTES 20864

__device__ uint2 g_WiF[32*16*2*32];   // [i][j][kk][lane] 256KB
__device__ uint4 g_W1F[16*4*32];      // [j][kkp][lane]   32KB
__device__ uint4 g_W2F[16*4*32];      // 32KB
__device__ float g_w32[32*128];       // Wi[:,32] per step 16KB
__device__ uint2 g_b1p[32];           // b1 packed bf16x2: [jp][tq] -> (lo pair, hi pair)
__device__ unsigned g_ticket[1024];   // per-SM arrival counter

static __device__ __forceinline__ uint32_t pack_bf2(float lo, float hi){
    __nv_bfloat162 p = __floats2bfloat162_rn(lo, hi);
    return *(uint32_t*)&p;
}
static __device__ __forceinline__ uint32_t hmul2u(uint32_t a, uint32_t b){
    __nv_bfloat162 r = __hmul2(*(__nv_bfloat162*)&a, *(__nv_bfloat162*)&b);
    return *(uint32_t*)&r;
}
static __device__ __forceinline__ uint32_t hadd2u(uint32_t a, uint32_t b){
    __nv_bfloat162 r = __hadd2(*(__nv_bfloat162*)&a, *(__nv_bfloat162*)&b);
    return *(uint32_t*)&r;
}
static __device__ __forceinline__ uint32_t hmax2z(uint32_t a){
    __nv_bfloat162 zz; *(uint32_t*)&zz = 0u;
    __nv_bfloat162 r = __hmax2(*(__nv_bfloat162*)&a, zz);
    return *(uint32_t*)&r;
}
static __device__ __forceinline__ void mma_bf16(float* c, const uint32_t* a,
                                                uint32_t b0, uint32_t b1){
    asm volatile("mma.sync.aligned.m16n8k16.row.col.f32.bf16.bf16.f32 "
        "{%0,%1,%2,%3}, {%4,%5,%6,%7}, {%8,%9}, {%0,%1,%2,%3};"
        : "+f"(c[0]), "+f"(c[1]), "+f"(c[2]), "+f"(c[3])
        : "r"(a[0]), "r"(a[1]), "r"(a[2]), "r"(a[3]), "r"(b0), "r"(b1));
}
static __device__ __forceinline__ void mma_bf16_z(float* c, const uint32_t* a,
                                                  uint32_t b0, uint32_t b1){
    float zz = 0.f;
    asm volatile("mma.sync.aligned.m16n8k16.row.col.f32.bf16.bf16.f32 "
        "{%0,%1,%2,%3}, {%4,%5,%6,%7}, {%8,%9}, {%10,%10,%10,%10};"
        : "=f"(c[0]), "=f"(c[1]), "=f"(c[2]), "=f"(c[3])
        : "r"(a[0]), "r"(a[1]), "r"(a[2]), "r"(a[3]), "r"(b0), "r"(b1), "f"(zz));
}

// ---------------- prep: bake fragment images ----------------
__global__ void prep_frag(const float* __restrict__ Wi,
                          const float* __restrict__ W1,
                          const float* __restrict__ W2,
                          const float* __restrict__ b1){
    int idx = blockIdx.x * 256 + threadIdx.x;      // 32768 threads
    if (idx < 32*16*2*32){
        int lane = idx & 31, kk = (idx>>5)&1, j = (idx>>6)&15, i = idx>>10;
        int n = 8*j + (lane>>2), k0 = 16*kk + 2*(lane&3);
        const float* s = Wi + ((size_t)i*HD + n)*(XD+1);
        uint2 v;
        v.x = pack_bf2(s[k0],   s[k0+1]);
        v.y = pack_bf2(s[k0+8], s[k0+9]);
        g_WiF[idx] = v;
    }
    if (idx < 16*4*32){
        int lane = idx & 31, kkp = (idx>>5)&3, j = idx>>7;
        int n = 8*j + (lane>>2), kb = 32*kkp + 2*(lane&3);
        const float* s1 = W1 + n*HD;
        const float* s2 = W2 + n*HD;
        uint4 v1, v2;
        v1.x = pack_bf2(s1[kb],    s1[kb+1]);  v1.y = pack_bf2(s1[kb+8],  s1[kb+9]);
        v1.z = pack_bf2(s1[kb+16], s1[kb+17]); v1.w = pack_bf2(s1[kb+24], s1[kb+25]);
        v2.x = pack_bf2(s2[kb],    s2[kb+1]);  v2.y = pack_bf2(s2[kb+8],  s2[kb+9]);
        v2.z = pack_bf2(s2[kb+16], s2[kb+17]); v2.w = pack_bf2(s2[kb+24], s2[kb+25]);
        g_W1F[idx] = v1;
        g_W2F[idx] = v2;
    }
    if (idx < 32*128){
        int i = idx >> 7, n = idx & 127;
        g_w32[idx] = Wi[((size_t)i*HD + n)*(XD+1) + XD];
    }
    if (idx < 32){                      // b1 packed: [jp][tq]
        int jp = idx >> 2, tq = idx & 3;
        uint2 v;
        v.x = pack_bf2(b1[16*jp + 2*tq],     b1[16*jp + 2*tq + 1]);
        v.y = pack_bf2(b1[16*jp + 8 + 2*tq], b1[16*jp + 8 + 2*tq + 1]);
        g_b1p[idx] = v;
    }
}

// ---------------- main ----------------
__global__ void __launch_bounds__(TPB, 2) gen_causal_nf(
    const float* __restrict__ x,  const float* __restrict__ z,
    const float* __restrict__ M,
    const float* __restrict__ bi, const float* __restrict__ wf,
    const float* __restrict__ bf,
    const float* __restrict__ b1, const float* __restrict__ b2,
    float* __restrict__ out, int B)
{
    extern __shared__ char base[];
    char* ZTp = base + OFF_ZT;
    char* OXp = base + OFF_OX;
    char* MBp = base + OFF_MB;

    const int t    = threadIdx.x;
    const int lane = t & 31;
    const int warp = t >> 5;
    const int wbase = warp * 32;
    const int tq = lane & 3;
    const int g  = lane >> 2;
    const int ctaRow = blockIdx.x * ROWS;
    const int row = ctaRow + t;
    const bool active = (row < B);

    // ---- per-SM co-residency ticket ----
    if (t == 0){
        uint32_t smid;
        asm volatile("mov.u32 %0, %%smid;" : "=r"(smid));
        unsigned tk = atomicAdd(&g_ticket[smid & 1023], 1u);
        *(unsigned*)(base + OFF_TK) = tk;
    }

    // ---- one-time init ----
    #pragma unroll 4
    for (int it = 0; it < 32; it++){
        int idx = it * TPB + t;                   // 4096 = 128x32
        int r = idx >> 5, c = idx & 31;
        float v = (ctaRow + r < B) ? z[(size_t)(ctaRow + r)*XD + c] : 0.f;
        __nv_bfloat16 h = __float2bfloat16(v);
        *(uint16_t*)(ZTp + r*66 + c*2) = *(uint16_t*)&h;
    }
    for (int idx = t; idx < 512; idx += TPB){
        int col = idx >> 4, p = idx & 15;
        *(uint32_t*)(MBp + col*64 + p*4) =
            pack_bf2(M[(2*p)*XD + col], M[(2*p+1)*XD + col]);
    }
    {
        uint32_t* oxr = (uint32_t*)(OXp + t*80);
        if (active){
            #pragma unroll
            for (int q = 0; q < 4; q++){
                float4 v = *(const float4*)(x + (size_t)row*XD + 4*q);
                oxr[2*q]   = pack_bf2(v.x, v.y);
                oxr[2*q+1] = pack_bf2(v.z, v.w);
            }
        } else {
            #pragma unroll
            for (int q = 0; q < 8; q++) oxr[q] = 0u;
        }
    }
    __syncthreads();   // the ONLY cta-wide sync

    // ---- anti-phase burn: odd-slot CTAs start ~half a step late ----
    if ((*(volatile unsigned*)(base + OFF_TK)) & 1u){
        float acc = (float)t * 1e-20f;
        for (int k = 0; k < 2400; k++)
            asm volatile("fma.rn.f32 %0, %0, %1, %2;"
                         : "+f"(acc) : "f"(1.0000001f), "f"(1e-30f));
        if (acc > 1e10f) ((volatile float*)base)[0] = acc;  // never true
    }

    const int rg0 = wbase + g;        // m=0 rows: rg0, rg0+8
    const int rg1 = wbase + 16 + g;   // m=1 rows

    uint32_t A [2][8][4];   // fc output  (mlp1 input)
    uint32_t A2[2][8][4];   // mlp1 output (mlp2 input)

    for (int i = 0; i < XD; i++){
        // ---- fc A-frags directly from OX ⊙ M (warp-local rows) ----
        uint32_t afc[2][2][4];
        #pragma unroll
        for (int m = 0; m < 2; m++){
            int rg = m ? rg1 : rg0;
            #pragma unroll
            for (int kk = 0; kk < 2; kk++){
                uint32_t mlo = *(const uint32_t*)(MBp + i*64 + (8*kk+tq)*4);
                uint32_t mhi = *(const uint32_t*)(MBp + i*64 + (8*kk+4+tq)*4);
                afc[m][kk][0] = hmul2u(*(const uint32_t*)(OXp + rg*80 + kk*32 + tq*4),          mlo);
                afc[m][kk][1] = hmul2u(*(const uint32_t*)(OXp + (rg+8)*80 + kk*32 + tq*4),      mlo);
                afc[m][kk][2] = hmul2u(*(const uint32_t*)(OXp + rg*80 + kk*32 + 16 + tq*4),     mhi);
                afc[m][kk][3] = hmul2u(*(const uint32_t*)(OXp + (rg+8)*80 + kk*32 + 16 + tq*4), mhi);
            }
        }

        float zf[2][2];
        #pragma unroll
        for (int m = 0; m < 2; m++){
            int rg = m ? rg1 : rg0;
            zf[m][0] = __bfloat162float(*(const __nv_bfloat16*)(ZTp + rg*66 + 2*i));
            zf[m][1] = __bfloat162float(*(const __nv_bfloat16*)(ZTp + (rg+8)*66 + 2*i));
        }

        // ================= fc (K=32), two j-halves =================
        #pragma unroll
        for (int h = 0; h < 2; h++){
            float C8[2][8][4];
            const uint2* wif = g_WiF + (size_t)i*16*2*32;
            #pragma unroll
            for (int jj = 0; jj < 8; jj++){
                uint2 w0 = __ldg(&wif[((8*h+jj)*2 + 0)*32 + lane]);
                uint2 w1 = __ldg(&wif[((8*h+jj)*2 + 1)*32 + lane]);
                mma_bf16_z(C8[0][jj], afc[0][0], w0.x, w0.y);
                mma_bf16 (C8[0][jj], afc[0][1], w1.x, w1.y);
                mma_bf16_z(C8[1][jj], afc[1][0], w0.x, w0.y);
                mma_bf16 (C8[1][jj], afc[1][1], w1.x, w1.y);
            }
            // fc epilogue (packed): A = hmax2(hadd2(pack(C), pack(z*w32+bi)))
            #pragma unroll
            for (int q = 0; q < 4; q++){
                int jp = 4*h + q;
                float2 blo = __ldg((const float2*)(bi + i*HD + 16*jp + 2*tq));
                float2 bhi = __ldg((const float2*)(bi + i*HD + 16*jp + 8 + 2*tq));
                float2 wlo = __ldg((const float2*)(g_w32 + i*HD + 16*jp + 2*tq));
                float2 whi = __ldg((const float2*)(g_w32 + i*HD + 16*jp + 8 + 2*tq));
                #pragma unroll
                for (int m = 0; m < 2; m++){
                    uint32_t tl0 = pack_bf2(fmaf(zf[m][0], wlo.x, blo.x), fmaf(zf[m][0], wlo.y, blo.y));
                    uint32_t tl1 = pack_bf2(fmaf(zf[m][1], wlo.x, blo.x), fmaf(zf[m][1], wlo.y, blo.y));
                    uint32_t ul0 = pack_bf2(fmaf(zf[m][0], whi.x, bhi.x), fmaf(zf[m][0], whi.y, bhi.y));
                    uint32_t ul1 = pack_bf2(fmaf(zf[m][1], whi.x, bhi.x), fmaf(zf[m][1], whi.y, bhi.y));
                    const float* c0 = C8[m][2*q];
                    const float* c1 = C8[m][2*q+1];
                    A[m][jp][0] = hmax2z(hadd2u(pack_bf2(c0[0], c0[1]), tl0));
                    A[m][jp][1] = hmax2z(hadd2u(pack_bf2(c0[2], c0[3]), tl1));
                    A[m][jp][2] = hmax2z(hadd2u(pack_bf2(c1[0], c1[1]), ul0));
                    A[m][jp][3] = hmax2z(hadd2u(pack_bf2(c1[2], c1[3]), ul1));
                }
            }
        }

        // ================= MLP1 (W1, K=128), two j-halves =================
        #pragma unroll
        for (int h = 0; h < 2; h++){
            float C8[2][8][4];
            #pragma unroll
            for (int jj = 0; jj < 8; jj++){
                int j = 8*h + jj;
                #pragma unroll
                for (int kkp = 0; kkp < 4; kkp++){
                    uint4 bv = __ldg(&g_W1F[(j*4+kkp)*32 + lane]);
                    if (kkp == 0){
                        mma_bf16_z(C8[0][jj], A[0][0], bv.x, bv.y);
                        mma_bf16_z(C8[1][jj], A[1][0], bv.x, bv.y);
                    } else {
                        mma_bf16(C8[0][jj], A[0][2*kkp], bv.x, bv.y);
                        mma_bf16(C8[1][jj], A[1][2*kkp], bv.x, bv.y);
                    }
                    mma_bf16(C8[0][jj], A[0][2*kkp+1], bv.z, bv.w);
                    mma_bf16(C8[1][jj], A[1][2*kkp+1], bv.z, bv.w);
                }
            }
            // epilogue with pre-packed b1 -> A2 (packed math)
            #pragma unroll
            for (int q = 0; q < 4; q++){
                int jp = 4*h + q;
                uint2 bp = __ldg(&g_b1p[jp*4 + tq]);
                #pragma unroll
                for (int m = 0; m < 2; m++){
                    const float* c0 = C8[m][2*q];
                    const float* c1 = C8[m][2*q+1];
                    A2[m][jp][0] = hmax2z(hadd2u(pack_bf2(c0[0], c0[1]), bp.x));
                    A2[m][jp][1] = hmax2z(hadd2u(pack_bf2(c0[2], c0[3]), bp.x));
                    A2[m][jp][2] = hmax2z(hadd2u(pack_bf2(c1[0], c1[1]), bp.y));
                    A2[m][jp][3] = hmax2z(hadd2u(pack_bf2(c1[2], c1[3]), bp.y));
                }
            }
        }

        // ================= MLP2 (W2, K=128) + final dot, two j-halves ========
        float p0[2] = {0.f, 0.f}, p1[2] = {0.f, 0.f};
        #pragma unroll
        for (int h = 0; h < 2; h++){
            float C8[2][8][4];
            #pragma unroll
            for (int jj = 0; jj < 8; jj++){
                int j = 8*h + jj;
                #pragma unroll
                for (int kkp = 0; kkp < 4; kkp++){
                    uint4 bv = __ldg(&g_W2F[(j*4+kkp)*32 + lane]);
                    if (kkp == 0){
                        mma_bf16_z(C8[0][jj], A2[0][0], bv.x, bv.y);
                        mma_bf16_z(C8[1][jj], A2[1][0], bv.x, bv.y);
                    } else {
                        mma_bf16(C8[0][jj], A2[0][2*kkp], bv.x, bv.y);
                        mma_bf16(C8[1][jj], A2[1][2*kkp], bv.x, bv.y);
                    }
                    mma_bf16(C8[0][jj], A2[0][2*kkp+1], bv.z, bv.w);
                    mma_bf16(C8[1][jj], A2[1][2*kkp+1], bv.z, bv.w);
                }
            }
            // final-dot partial for this half (fp32)
            #pragma unroll
            for (int jj = 0; jj < 8; jj++){
                int j = 8*h + jj;
                float2 b2v = __ldg((const float2*)(b2 + 8*j + 2*tq));
                float2 wfv = __ldg((const float2*)(wf + i*HD + 8*j + 2*tq));
                #pragma unroll
                for (int m = 0; m < 2; m++){
                    p0[m] += fmaxf(C8[m][jj][0]+b2v.x, 0.f)*wfv.x
                           + fmaxf(C8[m][jj][1]+b2v.y, 0.f)*wfv.y;
                    p1[m] += fmaxf(C8[m][jj][2]+b2v.x, 0.f)*wfv.x
                           + fmaxf(C8[m][jj][3]+b2v.y, 0.f)*wfv.y;
                }
            }
        }

        // ---- sigmoid, state + out update ----
        {
            float bfv = __ldg(bf + i);
            #pragma unroll
            for (int m = 0; m < 2; m++){
                float q0 = p0[m], q1 = p1[m];
                q0 += __shfl_xor_sync(0xFFFFFFFFu, q0, 1);
                q0 += __shfl_xor_sync(0xFFFFFFFFu, q0, 2);
                q1 += __shfl_xor_sync(0xFFFFFFFFu, q1, 1);
                q1 += __shfl_xor_sync(0xFFFFFFFFu, q1, 2);
                if (tq == 0){
                    int lr0 = (m ? rg1 : rg0);
                    int lr1 = lr0 + 8;
                    float v0 = 1.f/(1.f + __expf(-(q0 + bfv)));
                    float v1 = 1.f/(1.f + __expf(-(q1 + bfv)));
                    __nv_bfloat16 h0 = __float2bfloat16(v0);
                    __nv_bfloat16 h1 = __float2bfloat16(v1);
                    *(uint16_t*)(OXp + lr0*80 + 2*i) = *(uint16_t*)&h0;
                    *(uint16_t*)(OXp + lr1*80 + 2*i) = *(uint16_t*)&h1;
                    int gr0 = ctaRow + lr0, gr1 = ctaRow + lr1;
                    if (gr0 < B) out[(size_t)gr0*XD + i] = v0;
                    if (gr1 < B) out[(size_t)gr1*XD + i] = v1;
                }
            }
        }
        __syncwarp();   // OX writes visible to this warp's next-step A-frag loads
    }
}

extern "C" void kernel_launch(void* const* d_in, const int* in_sizes, int n_in,
                              void* d_out, int out_size) {
    const float* x  = (const float*)d_in[0];
    const float* z  = (const float*)d_in[1];
    const float* M  = (const float*)d_in[2];
    const float* Wi = (const float*)d_in[3];
    const float* bi = (const float*)d_in[4];
    const float* wf = (const float*)d_in[5];
    const float* bf = (const float*)d_in[6];
    const float* W1 = (const float*)d_in[7];
    const float* b1 = (const float*)d_in[8];
    const float* W2 = (const float*)d_in[9];
    const float* b2 = (const float*)d_in[10];
    float* out = (float*)d_out;

    const int B = in_sizes[0] / XD;

    prep_frag<<<128, 256>>>(Wi, W1, W2, b1);

    cudaFuncSetAttribute(gen_causal_nf,
                         cudaFuncAttributeMaxDynamicSharedMemorySize, SMEM_BYTES);
    const int grid = (B + ROWS - 1) / ROWS;
    gen_causal_nf<<<grid, TPB, SMEM_BYTES>>>(x, z, M, bi, wf, bf,
                                             b1, b2, out, B);
}